// round 8
// baseline (speedup 1.0000x reference)
#include <cuda_runtime.h>
#include <math.h>

// ---------------- problem constants ----------------
#define B_   8
#define C_   512
#define C4_  128
#define H_   1024
#define W_   8
#define HW_  8192           // H_*W_
#define NSL_ 64             // B_*W_  (number of (b,w) attention slices)

// ---------------- GEMM tile constants ----------------
#define BM 128
#define BN 128
#define BK 16
#define AST 132             // padded A-tile stride (bank-conflict relief, 16B aligned)

// ---------------- scratch (device globals: no cudaMalloc allowed) ----------------
__device__ float g_qT [8388608];    // [b][w][d][h]   = 64*128*1024   (32 MB)
__device__ float g_vT [33554432];   // [b][w][c][h]   = 64*512*1024   (128 MB)
__device__ float g_att[67108864];   // [b][w][i][j]   = 64*1024*1024  (256 MB)
__device__ float g_xrT[33554432];   // [b][w][c][h]   = 64*512*1024   (128 MB)
__device__ float g_chan[2 * C_];    // channel sum / sumsq
__device__ float g_bn  [2 * C_];    // scale / shift

// =====================================================================
// Kernel 1/2: projections. out[b,w,m,h] = sum_c Wm[m,c]*x[b,c,h,w] (+bias)
// A = Wm (row-major [M, C_]), B = x[b] ([C_, HW_], hw contiguous)
// =====================================================================
__global__ __launch_bounds__(256) void k_proj(const float* __restrict__ Wm,
                                              const float* __restrict__ xg,
                                              const float* __restrict__ bias,
                                              int M, int which)
{
    __shared__ __align__(16) float As[BK][AST];
    __shared__ __align__(16) float Bs[BK][BN];
    const int tid = threadIdx.x;
    const int tx = tid & 15, ty = tid >> 4;
    const int bb = blockIdx.z;
    const int n0 = blockIdx.x * BN;
    const int m0 = blockIdx.y * BM;
    const float* Bp = xg + (size_t)bb * C_ * HW_;
    float* outT = which ? g_vT : g_qT;

    float acc[8][8];
#pragma unroll
    for (int i = 0; i < 8; ++i)
#pragma unroll
        for (int j = 0; j < 8; ++j) acc[i][j] = 0.f;

    const int ar = tid >> 2;            // 0..63  (A rows: ar, ar+64)
    const int ak = (tid & 3) << 2;      // 0,4,8,12
    const int br = tid >> 5;            // 0..7   (B rows: br, br+8)
    const int bc = (tid & 31) << 2;     // 0..124

    for (int kt = 0; kt < C_; kt += BK) {
        float4 a0 = *(const float4*)(Wm + (size_t)(m0 + ar)      * C_  + kt + ak);
        float4 a1 = *(const float4*)(Wm + (size_t)(m0 + ar + 64) * C_  + kt + ak);
        float4 b0 = *(const float4*)(Bp + (size_t)(kt + br)      * HW_ + n0 + bc);
        float4 b1 = *(const float4*)(Bp + (size_t)(kt + br + 8)  * HW_ + n0 + bc);
        __syncthreads();
        As[ak + 0][ar]      = a0.x; As[ak + 1][ar]      = a0.y;
        As[ak + 2][ar]      = a0.z; As[ak + 3][ar]      = a0.w;
        As[ak + 0][ar + 64] = a1.x; As[ak + 1][ar + 64] = a1.y;
        As[ak + 2][ar + 64] = a1.z; As[ak + 3][ar + 64] = a1.w;
        *(float4*)&Bs[br][bc]     = b0;
        *(float4*)&Bs[br + 8][bc] = b1;
        __syncthreads();
#pragma unroll
        for (int k = 0; k < BK; ++k) {
            float a[8], b[8];
            *(float4*)&a[0] = *(const float4*)&As[k][ty * 4];
            *(float4*)&a[4] = *(const float4*)&As[k][64 + ty * 4];
            *(float4*)&b[0] = *(const float4*)&Bs[k][tx * 4];
            *(float4*)&b[4] = *(const float4*)&Bs[k][64 + tx * 4];
#pragma unroll
            for (int i = 0; i < 8; ++i)
#pragma unroll
                for (int j = 0; j < 8; ++j)
                    acc[i][j] = fmaf(a[i], b[j], acc[i][j]);
        }
    }

#pragma unroll
    for (int i = 0; i < 8; ++i) {
        const int m = m0 + ((i < 4) ? (ty * 4 + i) : (64 + ty * 4 + i - 4));
        const float bv = bias ? bias[m] : 0.f;
#pragma unroll
        for (int j = 0; j < 8; ++j) {
            const int n = n0 + ((j < 4) ? (tx * 4 + j) : (64 + tx * 4 + j - 4));
            const int w = n & 7, h = n >> 3;
            outT[(((size_t)bb * W_ + w) * M + m) * H_ + h] = acc[i][j] + bv;
        }
    }
}

// =====================================================================
// Kernel 3: energy.  E[i,j] = sum_d Q[d,i]*Q[d,j]  per slice (TN gemm)
// =====================================================================
__global__ __launch_bounds__(256) void k_energy()
{
    __shared__ __align__(16) float As[BK][AST];
    __shared__ __align__(16) float Bs[BK][BN];
    const int tid = threadIdx.x;
    const int tx = tid & 15, ty = tid >> 4;
    const int s  = blockIdx.z;
    const int n0 = blockIdx.x * BN;   // j
    const int m0 = blockIdx.y * BM;   // i
    const float* Q = g_qT + (size_t)s * C4_ * H_;   // [128][1024]

    float acc[8][8];
#pragma unroll
    for (int i = 0; i < 8; ++i)
#pragma unroll
        for (int j = 0; j < 8; ++j) acc[i][j] = 0.f;

    const int r  = tid >> 5;
    const int c4 = (tid & 31) << 2;

    for (int kt = 0; kt < C4_; kt += BK) {
        float4 a0 = *(const float4*)(Q + (size_t)(kt + r)     * H_ + m0 + c4);
        float4 a1 = *(const float4*)(Q + (size_t)(kt + r + 8) * H_ + m0 + c4);
        float4 b0 = *(const float4*)(Q + (size_t)(kt + r)     * H_ + n0 + c4);
        float4 b1 = *(const float4*)(Q + (size_t)(kt + r + 8) * H_ + n0 + c4);
        __syncthreads();
        *(float4*)&As[r][c4]     = a0;
        *(float4*)&As[r + 8][c4] = a1;
        *(float4*)&Bs[r][c4]     = b0;
        *(float4*)&Bs[r + 8][c4] = b1;
        __syncthreads();
#pragma unroll
        for (int k = 0; k < BK; ++k) {
            float a[8], b[8];
            *(float4*)&a[0] = *(const float4*)&As[k][ty * 4];
            *(float4*)&a[4] = *(const float4*)&As[k][64 + ty * 4];
            *(float4*)&b[0] = *(const float4*)&Bs[k][tx * 4];
            *(float4*)&b[4] = *(const float4*)&Bs[k][64 + tx * 4];
#pragma unroll
            for (int i = 0; i < 8; ++i)
#pragma unroll
                for (int j = 0; j < 8; ++j)
                    acc[i][j] = fmaf(a[i], b[j], acc[i][j]);
        }
    }

    float* E = g_att + (size_t)s * H_ * H_;
#pragma unroll
    for (int i = 0; i < 8; ++i) {
        const int m = m0 + ((i < 4) ? (ty * 4 + i) : (64 + ty * 4 + i - 4));
        *(float4*)(E + (size_t)m * H_ + n0 + tx * 4)      = make_float4(acc[i][0], acc[i][1], acc[i][2], acc[i][3]);
        *(float4*)(E + (size_t)m * H_ + n0 + 64 + tx * 4) = make_float4(acc[i][4], acc[i][5], acc[i][6], acc[i][7]);
    }
}

// =====================================================================
// Kernel 4: column softmax over i (rows) for each j, in place, + renorm
// One thread per column j -> fully coalesced. Online max/sum, 2R+1W.
// =====================================================================
__global__ void k_softmax()
{
    const int j = blockIdx.x * 256 + threadIdx.x;
    const int s = blockIdx.y;
    float* p = g_att + (size_t)s * H_ * H_ + j;

    float m = -3.0e38f, sum = 0.f;
    for (int i = 0; i < H_; i += 8) {
        float v[8];
#pragma unroll
        for (int e = 0; e < 8; ++e) v[e] = p[(size_t)(i + e) * H_];
        float lm = v[0];
#pragma unroll
        for (int e = 1; e < 8; ++e) lm = fmaxf(lm, v[e]);
        const float mn = fmaxf(m, lm);
        float ls = 0.f;
#pragma unroll
        for (int e = 0; e < 8; ++e) ls += __expf(v[e] - mn);
        sum = sum * __expf(m - mn) + ls;
        m = mn;
    }
    // softmax then L1 renorm: exact softmax sum is 1, so renorm divides by (1+1e-9)
    const float inv = 1.0f / (sum * (1.0f + 1e-9f));
    for (int i = 0; i < H_; i += 8) {
        float v[8];
#pragma unroll
        for (int e = 0; e < 8; ++e) v[e] = p[(size_t)(i + e) * H_];
#pragma unroll
        for (int e = 0; e < 8; ++e) p[(size_t)(i + e) * H_] = __expf(v[e] - m) * inv;
    }
}

// =====================================================================
// Kernel 5: apply attention.  xrT[c,j] = sum_i V[c,i]*att[i,j]  (NN gemm)
// =====================================================================
__global__ __launch_bounds__(256) void k_apply()
{
    __shared__ __align__(16) float As[BK][AST];
    __shared__ __align__(16) float Bs[BK][BN];
    const int tid = threadIdx.x;
    const int tx = tid & 15, ty = tid >> 4;
    const int s  = blockIdx.z;
    const int n0 = blockIdx.x * BN;   // j
    const int m0 = blockIdx.y * BM;   // c
    const float* V  = g_vT  + (size_t)s * C_ * H_;   // [512][1024]
    const float* Am = g_att + (size_t)s * H_ * H_;   // [1024][1024]

    float acc[8][8];
#pragma unroll
    for (int i = 0; i < 8; ++i)
#pragma unroll
        for (int j = 0; j < 8; ++j) acc[i][j] = 0.f;

    const int ar = tid >> 2;
    const int ak = (tid & 3) << 2;
    const int br = tid >> 5;
    const int bc = (tid & 31) << 2;

    for (int kt = 0; kt < H_; kt += BK) {
        float4 a0 = *(const float4*)(V  + (size_t)(m0 + ar)      * H_ + kt + ak);
        float4 a1 = *(const float4*)(V  + (size_t)(m0 + ar + 64) * H_ + kt + ak);
        float4 b0 = *(const float4*)(Am + (size_t)(kt + br)      * H_ + n0 + bc);
        float4 b1 = *(const float4*)(Am + (size_t)(kt + br + 8)  * H_ + n0 + bc);
        __syncthreads();
        As[ak + 0][ar]      = a0.x; As[ak + 1][ar]      = a0.y;
        As[ak + 2][ar]      = a0.z; As[ak + 3][ar]      = a0.w;
        As[ak + 0][ar + 64] = a1.x; As[ak + 1][ar + 64] = a1.y;
        As[ak + 2][ar + 64] = a1.z; As[ak + 3][ar + 64] = a1.w;
        *(float4*)&Bs[br][bc]     = b0;
        *(float4*)&Bs[br + 8][bc] = b1;
        __syncthreads();
#pragma unroll
        for (int k = 0; k < BK; ++k) {
            float a[8], b[8];
            *(float4*)&a[0] = *(const float4*)&As[k][ty * 4];
            *(float4*)&a[4] = *(const float4*)&As[k][64 + ty * 4];
            *(float4*)&b[0] = *(const float4*)&Bs[k][tx * 4];
            *(float4*)&b[4] = *(const float4*)&Bs[k][64 + tx * 4];
#pragma unroll
            for (int i = 0; i < 8; ++i)
#pragma unroll
                for (int j = 0; j < 8; ++j)
                    acc[i][j] = fmaf(a[i], b[j], acc[i][j]);
        }
    }

    float* O = g_xrT + (size_t)s * C_ * H_;
#pragma unroll
    for (int i = 0; i < 8; ++i) {
        const int m = m0 + ((i < 4) ? (ty * 4 + i) : (64 + ty * 4 + i - 4));
        *(float4*)(O + (size_t)m * H_ + n0 + tx * 4)      = make_float4(acc[i][0], acc[i][1], acc[i][2], acc[i][3]);
        *(float4*)(O + (size_t)m * H_ + n0 + 64 + tx * 4) = make_float4(acc[i][4], acc[i][5], acc[i][6], acc[i][7]);
    }
}

// =====================================================================
// Kernel 6: t = t_w @ (x - x_r) + t_b   -> d_out (original [B,C,H,W] layout)
// =====================================================================
__global__ __launch_bounds__(256) void k_trans(const float* __restrict__ t_w,
                                               const float* __restrict__ t_b,
                                               const float* __restrict__ xg,
                                               float* __restrict__ out)
{
    __shared__ __align__(16) float As[BK][AST];
    __shared__ __align__(16) float Bs[BK][BN];
    const int tid = threadIdx.x;
    const int tx = tid & 15, ty = tid >> 4;
    const int bb = blockIdx.z;
    const int n0 = blockIdx.x * BN;
    const int m0 = blockIdx.y * BM;
    const float* Xp = xg + (size_t)bb * C_ * HW_;

    float acc[8][8];
#pragma unroll
    for (int i = 0; i < 8; ++i)
#pragma unroll
        for (int j = 0; j < 8; ++j) acc[i][j] = 0.f;

    const int ar = tid >> 2;
    const int ak = (tid & 3) << 2;
    const int br = tid >> 5;
    const int bc = (tid & 31) << 2;

    for (int kt = 0; kt < C_; kt += BK) {
        float4 a0 = *(const float4*)(t_w + (size_t)(m0 + ar)      * C_ + kt + ak);
        float4 a1 = *(const float4*)(t_w + (size_t)(m0 + ar + 64) * C_ + kt + ak);
        float4 b0, b1;
        {
            const int c0 = kt + br;
            float4 xv = *(const float4*)(Xp + (size_t)c0 * HW_ + n0 + bc);
            float tvals[4];
#pragma unroll
            for (int e = 0; e < 4; ++e) {
                const int n = n0 + bc + e;
                const int w = n & 7, h = n >> 3;
                tvals[e] = ((const float*)&xv)[e]
                         - g_xrT[(((size_t)bb * W_ + w) * C_ + c0) * H_ + h];
            }
            b0 = make_float4(tvals[0], tvals[1], tvals[2], tvals[3]);
        }
        {
            const int c1 = kt + br + 8;
            float4 xv = *(const float4*)(Xp + (size_t)c1 * HW_ + n0 + bc);
            float tvals[4];
#pragma unroll
            for (int e = 0; e < 4; ++e) {
                const int n = n0 + bc + e;
                const int w = n & 7, h = n >> 3;
                tvals[e] = ((const float*)&xv)[e]
                         - g_xrT[(((size_t)bb * W_ + w) * C_ + c1) * H_ + h];
            }
            b1 = make_float4(tvals[0], tvals[1], tvals[2], tvals[3]);
        }
        __syncthreads();
        As[ak + 0][ar]      = a0.x; As[ak + 1][ar]      = a0.y;
        As[ak + 2][ar]      = a0.z; As[ak + 3][ar]      = a0.w;
        As[ak + 0][ar + 64] = a1.x; As[ak + 1][ar + 64] = a1.y;
        As[ak + 2][ar + 64] = a1.z; As[ak + 3][ar + 64] = a1.w;
        *(float4*)&Bs[br][bc]     = b0;
        *(float4*)&Bs[br + 8][bc] = b1;
        __syncthreads();
#pragma unroll
        for (int k = 0; k < BK; ++k) {
            float a[8], b[8];
            *(float4*)&a[0] = *(const float4*)&As[k][ty * 4];
            *(float4*)&a[4] = *(const float4*)&As[k][64 + ty * 4];
            *(float4*)&b[0] = *(const float4*)&Bs[k][tx * 4];
            *(float4*)&b[4] = *(const float4*)&Bs[k][64 + tx * 4];
#pragma unroll
            for (int i = 0; i < 8; ++i)
#pragma unroll
                for (int j = 0; j < 8; ++j)
                    acc[i][j] = fmaf(a[i], b[j], acc[i][j]);
        }
    }

    float* Op = out + (size_t)bb * C_ * HW_;
#pragma unroll
    for (int i = 0; i < 8; ++i) {
        const int m = m0 + ((i < 4) ? (ty * 4 + i) : (64 + ty * 4 + i - 4));
        const float bv = t_b[m];
        *(float4*)(Op + (size_t)m * HW_ + n0 + tx * 4) =
            make_float4(acc[i][0] + bv, acc[i][1] + bv, acc[i][2] + bv, acc[i][3] + bv);
        *(float4*)(Op + (size_t)m * HW_ + n0 + 64 + tx * 4) =
            make_float4(acc[i][4] + bv, acc[i][5] + bv, acc[i][6] + bv, acc[i][7] + bv);
    }
}

// =====================================================================
// BN statistics + finalize + residual/ReLU
// =====================================================================
__global__ void k_zero() { if (threadIdx.x < 2 * C_) g_chan[threadIdx.x] = 0.f; }

__global__ void k_chansum(const float* __restrict__ t)
{
    const int c = blockIdx.x, b = blockIdx.y;
    const float4* p = (const float4*)(t + ((size_t)b * C_ + c) * HW_);
    float s = 0.f, q = 0.f;
    for (int i = threadIdx.x; i < HW_ / 4; i += 256) {
        float4 v = p[i];
        s += v.x + v.y + v.z + v.w;
        q += v.x * v.x + v.y * v.y + v.z * v.z + v.w * v.w;
    }
    __shared__ float ss[256], sq[256];
    ss[threadIdx.x] = s; sq[threadIdx.x] = q;
    __syncthreads();
    for (int o = 128; o > 0; o >>= 1) {
        if (threadIdx.x < o) {
            ss[threadIdx.x] += ss[threadIdx.x + o];
            sq[threadIdx.x] += sq[threadIdx.x + o];
        }
        __syncthreads();
    }
    if (threadIdx.x == 0) {
        atomicAdd(&g_chan[c],      ss[0]);
        atomicAdd(&g_chan[C_ + c], sq[0]);
    }
}

__global__ void k_bnfin(const float* __restrict__ gamma, const float* __restrict__ beta)
{
    const int c = threadIdx.x;
    const float n = (float)(B_ * HW_);
    const float mean = g_chan[c] / n;
    const float var  = g_chan[C_ + c] / n - mean * mean;   // biased variance
    const float sc = gamma[c] * rsqrtf(var + 1e-5f);
    g_bn[c]      = sc;
    g_bn[C_ + c] = beta[c] - mean * sc;
}

__global__ void k_final(const float* __restrict__ xg, float* __restrict__ out)
{
    const size_t i4 = (size_t)blockIdx.x * 256 + threadIdx.x;
    const int c = (int)((i4 >> 11) & 511);   // 2048 float4 per (b,c)
    const float sc = g_bn[c], sh = g_bn[C_ + c];
    float4 t  = ((const float4*)out)[i4];
    float4 xv = ((const float4*)xg)[i4];
    float4 o;
    o.x = xv.x + fmaxf(0.f, fmaf(t.x, sc, sh));
    o.y = xv.y + fmaxf(0.f, fmaf(t.y, sc, sh));
    o.z = xv.z + fmaxf(0.f, fmaf(t.z, sc, sh));
    o.w = xv.w + fmaxf(0.f, fmaf(t.w, sc, sh));
    ((float4*)out)[i4] = o;
}

// =====================================================================
// launch
// =====================================================================
extern "C" void kernel_launch(void* const* d_in, const int* in_sizes, int n_in,
                              void* d_out, int out_size)
{
    (void)in_sizes; (void)n_in; (void)out_size;
    const float* x     = (const float*)d_in[0];
    const float* qk_w  = (const float*)d_in[1];
    const float* v_w   = (const float*)d_in[2];
    const float* v_b   = (const float*)d_in[3];
    const float* t_w   = (const float*)d_in[4];
    const float* t_b   = (const float*)d_in[5];
    const float* gamma = (const float*)d_in[6];
    const float* beta  = (const float*)d_in[7];
    float* out = (float*)d_out;

    k_zero   <<<1, 1024>>>();
    k_proj   <<<dim3(HW_ / BN, C4_ / BM, B_),  256>>>(qk_w, x, nullptr, C4_, 0);
    k_proj   <<<dim3(HW_ / BN, C_  / BM, B_),  256>>>(v_w,  x, v_b,     C_,  1);
    k_energy <<<dim3(H_  / BN, H_  / BM, NSL_), 256>>>();
    k_softmax<<<dim3(H_ / 256, NSL_),           256>>>();
    k_apply  <<<dim3(H_  / BN, C_  / BM, NSL_), 256>>>();
    k_trans  <<<dim3(HW_ / BN, C_  / BM, B_),   256>>>(t_w, t_b, x, out);
    k_chansum<<<dim3(C_, B_),                   256>>>(out);
    k_bnfin  <<<1, C_>>>(gamma, beta);
    k_final  <<<(B_ * C_ * HW_) / 4 / 256,      256>>>(x, out);
}

// round 16
// speedup vs baseline: 1.2303x; 1.2303x over previous
#include <cuda_runtime.h>
#include <cuda_bf16.h>
#include <math.h>
#include <stdint.h>

// ---------------- problem constants ----------------
#define B_   8
#define C_   512
#define C4_  128
#define H_   1024
#define W_   8
#define HW_  8192
#define NSL_ 64

// ---------------- FFMA GEMM tile constants ----------------
#define BM 128
#define BN 128
#define BK 16
#define AST 132

// ---------------- scratch ----------------
__device__ float g_qT [8388608];    // [b][w][h][d]  (d contiguous)      32 MB
__device__ float g_vT [33554432];   // [b][w][c][h]                     128 MB
__device__ float g_att[67108864];   // E[i][j] -> attT[j][i] in place   256 MB
__device__ float g_xrT[33554432];   // [b][w][c][h]                     128 MB
__device__ float g_chan[2 * C_];
__device__ float g_bn  [2 * C_];

// =====================================================================
// bf16x3 mma.sync GEMM:  C[m,n] = sum_k A[z][m,k] * B[z][n,k]
// CTA 128x128, 8 warps (32x64 each), K-chunk 32, double-buffered smem.
// mode 0: energy (A=B=q[s][h][d], K=128, out=E[i][j])
// mode 1: apply  (A=V[s][c][h],  B=attT[s][j][i], K=1024, out=xr[s][c][j])
// =====================================================================
#define PADK  40            // bf16 per smem row (32 data + 8 pad)
#define PADB  80            // bytes per smem row
#define ARR_B 10240         // 128 * PADB
#define STG_B 40960         // 4 arrays per stage
#define DYN_SMEM (2 * STG_B)

__device__ __forceinline__ uint32_t pk_hi(float a, float b) {
    __nv_bfloat162 h = __floats2bfloat162_rn(a, b);
    return *(uint32_t*)&h;
}
__device__ __forceinline__ void split2(float a, float b, uint32_t& hi, uint32_t& lo) {
    __nv_bfloat16 ha = __float2bfloat16(a);
    __nv_bfloat16 hb = __float2bfloat16(b);
    float la = a - __bfloat162float(ha);
    float lb = b - __bfloat162float(hb);
    __nv_bfloat162 h2; h2.x = ha; h2.y = hb;
    hi = *(uint32_t*)&h2;
    __nv_bfloat162 l2 = __floats2bfloat162_rn(la, lb);
    lo = *(uint32_t*)&l2;
}

#define MMA_BF16(c0,c1,c2,c3,a0,a1,a2,a3,b0,b1)                              \
    asm volatile(                                                            \
        "mma.sync.aligned.m16n8k16.row.col.f32.bf16.bf16.f32 "               \
        "{%0,%1,%2,%3}, {%4,%5,%6,%7}, {%8,%9}, {%0,%1,%2,%3};"              \
        : "+f"(c0), "+f"(c1), "+f"(c2), "+f"(c3)                             \
        : "r"(a0), "r"(a1), "r"(a2), "r"(a3), "r"(b0), "r"(b1))

__global__ __launch_bounds__(256, 1) void k_hmma(int mode)
{
    extern __shared__ char sm[];

    const float *A, *Bm;
    float* O;
    long sA, sB, sO;
    int lda, ldb, ldo, K;
    if (mode == 0) {
        A = g_qT; Bm = g_qT; O = g_att;
        sA = sB = (long)H_ * C4_; lda = ldb = C4_;
        sO = (long)H_ * H_; ldo = H_; K = C4_;
    } else {
        A = g_vT; Bm = g_att; O = g_xrT;
        sA = (long)C_ * H_; lda = H_;
        sB = (long)H_ * H_; ldb = H_;
        sO = (long)C_ * H_; ldo = H_; K = H_;
    }

    const int tid  = threadIdx.x;
    const int lane = tid & 31, wid = tid >> 5;
    const int wm = wid >> 1, wn = wid & 1;       // warp grid 4(m) x 2(n)
    const int g  = lane >> 2;                    // 0..7
    const int l2 = (lane & 3) * 2;               // 0,2,4,6
    const int z  = blockIdx.z;
    const int n0 = blockIdx.x * 128;
    const int m0 = blockIdx.y * 128;

    const float* Ab = A  + (size_t)z * sA + (size_t)m0 * lda;
    const float* Bb = Bm + (size_t)z * sB + (size_t)n0 * ldb;

    // staging: thread -> (row = tid>>1, k-half = (tid&1)*16), 4 float4 each operand
    const int r     = tid >> 1;
    const int halfk = (tid & 1) * 16;

    float acc[2][8][4];
#pragma unroll
    for (int mt = 0; mt < 2; ++mt)
#pragma unroll
        for (int nt = 0; nt < 8; ++nt)
#pragma unroll
            for (int e = 0; e < 4; ++e) acc[mt][nt][e] = 0.f;

    const int niter = K / 32;

    // ---- stage chunk 0 ----
    {
        const float* ga = Ab + (size_t)r * lda + halfk;
        const float* gb = Bb + (size_t)r * ldb + halfk;
        char* AH = sm;            char* AL = sm + ARR_B;
        char* BH = sm + 2*ARR_B;  char* BL = sm + 3*ARR_B;
        const int ob = r * PADB + halfk * 2;
#pragma unroll
        for (int q = 0; q < 4; ++q) {
            float4 va = *(const float4*)(ga + q * 4);
            uint32_t h0, l0, h1, l1;
            split2(va.x, va.y, h0, l0); split2(va.z, va.w, h1, l1);
            *(uint2*)(AH + ob + q * 8) = make_uint2(h0, h1);
            *(uint2*)(AL + ob + q * 8) = make_uint2(l0, l1);
            float4 vb = *(const float4*)(gb + q * 4);
            split2(vb.x, vb.y, h0, l0); split2(vb.z, vb.w, h1, l1);
            *(uint2*)(BH + ob + q * 8) = make_uint2(h0, h1);
            *(uint2*)(BL + ob + q * 8) = make_uint2(l0, l1);
        }
    }
    __syncthreads();

    for (int it = 0; it < niter; ++it) {
        // prefetch next chunk into registers
        float4 pa[4], pb[4];
        if (it + 1 < niter) {
            const float* ga = Ab + (size_t)r * lda + (it + 1) * 32 + halfk;
            const float* gb = Bb + (size_t)r * ldb + (it + 1) * 32 + halfk;
#pragma unroll
            for (int q = 0; q < 4; ++q) { pa[q] = *(const float4*)(ga + q * 4);
                                          pb[q] = *(const float4*)(gb + q * 4); }
        }

        // compute from current buffer
        {
            const char* base = sm + (it & 1) * STG_B;
            const char* AH = base;            const char* AL = base + ARR_B;
            const char* BH = base + 2*ARR_B;  const char* BL = base + 3*ARR_B;
#pragma unroll
            for (int ks = 0; ks < 2; ++ks) {
                const int kb2 = (ks * 16 + l2) * 2;
                uint32_t ah[2][4], al_[2][4];
#pragma unroll
                for (int mt = 0; mt < 2; ++mt) {
                    const int ro = (wm * 32 + mt * 16 + g) * PADB + kb2;
                    ah[mt][0]  = *(const uint32_t*)(AH + ro);
                    ah[mt][1]  = *(const uint32_t*)(AH + ro + 8 * PADB);
                    ah[mt][2]  = *(const uint32_t*)(AH + ro + 16);
                    ah[mt][3]  = *(const uint32_t*)(AH + ro + 8 * PADB + 16);
                    al_[mt][0] = *(const uint32_t*)(AL + ro);
                    al_[mt][1] = *(const uint32_t*)(AL + ro + 8 * PADB);
                    al_[mt][2] = *(const uint32_t*)(AL + ro + 16);
                    al_[mt][3] = *(const uint32_t*)(AL + ro + 8 * PADB + 16);
                }
#pragma unroll
                for (int nt = 0; nt < 8; ++nt) {
                    const int bo = (wn * 64 + nt * 8 + g) * PADB + kb2;
                    uint32_t bh0 = *(const uint32_t*)(BH + bo);
                    uint32_t bh1 = *(const uint32_t*)(BH + bo + 16);
                    uint32_t bl0 = *(const uint32_t*)(BL + bo);
                    uint32_t bl1 = *(const uint32_t*)(BL + bo + 16);
#pragma unroll
                    for (int mt = 0; mt < 2; ++mt) {
                        float* c = acc[mt][nt];
                        MMA_BF16(c[0], c[1], c[2], c[3],
                                 ah[mt][0], ah[mt][1], ah[mt][2], ah[mt][3], bh0, bh1);
                        MMA_BF16(c[0], c[1], c[2], c[3],
                                 ah[mt][0], ah[mt][1], ah[mt][2], ah[mt][3], bl0, bl1);
                        MMA_BF16(c[0], c[1], c[2], c[3],
                                 al_[mt][0], al_[mt][1], al_[mt][2], al_[mt][3], bh0, bh1);
                    }
                }
            }
        }

        // store prefetched chunk to other buffer
        if (it + 1 < niter) {
            char* base = sm + ((it + 1) & 1) * STG_B;
            char* AH = base;            char* AL = base + ARR_B;
            char* BH = base + 2*ARR_B;  char* BL = base + 3*ARR_B;
            const int ob = r * PADB + halfk * 2;
#pragma unroll
            for (int q = 0; q < 4; ++q) {
                uint32_t h0, l0, h1, l1;
                split2(pa[q].x, pa[q].y, h0, l0); split2(pa[q].z, pa[q].w, h1, l1);
                *(uint2*)(AH + ob + q * 8) = make_uint2(h0, h1);
                *(uint2*)(AL + ob + q * 8) = make_uint2(l0, l1);
                split2(pb[q].x, pb[q].y, h0, l0); split2(pb[q].z, pb[q].w, h1, l1);
                *(uint2*)(BH + ob + q * 8) = make_uint2(h0, h1);
                *(uint2*)(BL + ob + q * 8) = make_uint2(l0, l1);
            }
            __syncthreads();
        }
    }

    // epilogue
    float* Ob = O + (size_t)z * sO;
#pragma unroll
    for (int mt = 0; mt < 2; ++mt) {
        const int row = m0 + wm * 32 + mt * 16 + g;
#pragma unroll
        for (int nt = 0; nt < 8; ++nt) {
            const int col = n0 + wn * 64 + nt * 8 + l2;
            *(float2*)(Ob + (size_t)row * ldo + col)       = make_float2(acc[mt][nt][0], acc[mt][nt][1]);
            *(float2*)(Ob + (size_t)(row + 8) * ldo + col) = make_float2(acc[mt][nt][2], acc[mt][nt][3]);
        }
    }
}

// =====================================================================
// projections (FFMA). which==0 (q): out [s][h][d]; which==1 (v): [s][c][h]
// =====================================================================
__global__ __launch_bounds__(256) void k_proj(const float* __restrict__ Wm,
                                              const float* __restrict__ xg,
                                              const float* __restrict__ bias,
                                              int M, int which)
{
    __shared__ __align__(16) float As[BK][AST];
    __shared__ __align__(16) float Bs[BK][BN];
    const int tid = threadIdx.x;
    const int tx = tid & 15, ty = tid >> 4;
    const int bb = blockIdx.z;
    const int n0 = blockIdx.x * BN;
    const int m0 = blockIdx.y * BM;
    const float* Bp = xg + (size_t)bb * C_ * HW_;

    float acc[8][8];
#pragma unroll
    for (int i = 0; i < 8; ++i)
#pragma unroll
        for (int j = 0; j < 8; ++j) acc[i][j] = 0.f;

    const int ar = tid >> 2;
    const int ak = (tid & 3) << 2;
    const int br = tid >> 5;
    const int bc = (tid & 31) << 2;

    for (int kt = 0; kt < C_; kt += BK) {
        float4 a0 = *(const float4*)(Wm + (size_t)(m0 + ar)      * C_  + kt + ak);
        float4 a1 = *(const float4*)(Wm + (size_t)(m0 + ar + 64) * C_  + kt + ak);
        float4 b0 = *(const float4*)(Bp + (size_t)(kt + br)      * HW_ + n0 + bc);
        float4 b1 = *(const float4*)(Bp + (size_t)(kt + br + 8)  * HW_ + n0 + bc);
        __syncthreads();
        As[ak + 0][ar]      = a0.x; As[ak + 1][ar]      = a0.y;
        As[ak + 2][ar]      = a0.z; As[ak + 3][ar]      = a0.w;
        As[ak + 0][ar + 64] = a1.x; As[ak + 1][ar + 64] = a1.y;
        As[ak + 2][ar + 64] = a1.z; As[ak + 3][ar + 64] = a1.w;
        *(float4*)&Bs[br][bc]     = b0;
        *(float4*)&Bs[br + 8][bc] = b1;
        __syncthreads();
#pragma unroll
        for (int k = 0; k < BK; ++k) {
            float a[8], b[8];
            *(float4*)&a[0] = *(const float4*)&As[k][ty * 4];
            *(float4*)&a[4] = *(const float4*)&As[k][64 + ty * 4];
            *(float4*)&b[0] = *(const float4*)&Bs[k][tx * 4];
            *(float4*)&b[4] = *(const float4*)&Bs[k][64 + tx * 4];
#pragma unroll
            for (int i = 0; i < 8; ++i)
#pragma unroll
                for (int j = 0; j < 8; ++j)
                    acc[i][j] = fmaf(a[i], b[j], acc[i][j]);
        }
    }

#pragma unroll
    for (int i = 0; i < 8; ++i) {
        const int m = m0 + ((i < 4) ? (ty * 4 + i) : (64 + ty * 4 + i - 4));
        const float bv = bias ? bias[m] : 0.f;
#pragma unroll
        for (int j = 0; j < 8; ++j) {
            const int n = n0 + ((j < 4) ? (tx * 4 + j) : (64 + tx * 4 + j - 4));
            const int w = n & 7, h = n >> 3;
            if (which)
                g_vT[(((size_t)bb * W_ + w) * C_ + m) * H_ + h] = acc[i][j] + bv;
            else
                g_qT[(((size_t)bb * W_ + w) * H_ + h) * C4_ + m] = acc[i][j] + bv;
        }
    }
}

// =====================================================================
// Row softmax on symmetric E (E[i,j]==E[j,i] bitwise); writes attT[j][i]
// in place. Block j reads/writes only row j.
// =====================================================================
__global__ void k_softmax()
{
    const int j = blockIdx.x, s = blockIdx.y;
    float* row = g_att + ((size_t)s * H_ + j) * H_;
    const int tid = threadIdx.x, lane = tid & 31, wid = tid >> 5;
    __shared__ float rbuf[8];

    float4 v = ((const float4*)row)[tid];
    float m4 = fmaxf(fmaxf(v.x, v.y), fmaxf(v.z, v.w));
#pragma unroll
    for (int o = 16; o > 0; o >>= 1) m4 = fmaxf(m4, __shfl_xor_sync(0xffffffffu, m4, o));
    if (lane == 0) rbuf[wid] = m4;
    __syncthreads();
    float m = rbuf[0];
#pragma unroll
    for (int k = 1; k < 8; ++k) m = fmaxf(m, rbuf[k]);
    __syncthreads();

    float4 e;
    e.x = __expf(v.x - m); e.y = __expf(v.y - m);
    e.z = __expf(v.z - m); e.w = __expf(v.w - m);
    float s4 = e.x + e.y + e.z + e.w;
#pragma unroll
    for (int o = 16; o > 0; o >>= 1) s4 += __shfl_xor_sync(0xffffffffu, s4, o);
    if (lane == 0) rbuf[wid] = s4;
    __syncthreads();
    float sum = rbuf[0];
#pragma unroll
    for (int k = 1; k < 8; ++k) sum += rbuf[k];

    const float inv = 1.0f / (sum * (1.0f + 1e-9f));
    ((float4*)row)[tid] = make_float4(e.x * inv, e.y * inv, e.z * inv, e.w * inv);
}

// =====================================================================
// t = t_w @ (x - x_r) + t_b  -> d_out  (FFMA)
// =====================================================================
__global__ __launch_bounds__(256) void k_trans(const float* __restrict__ t_w,
                                               const float* __restrict__ t_b,
                                               const float* __restrict__ xg,
                                               float* __restrict__ out)
{
    __shared__ __align__(16) float As[BK][AST];
    __shared__ __align__(16) float Bs[BK][BN];
    const int tid = threadIdx.x;
    const int tx = tid & 15, ty = tid >> 4;
    const int bb = blockIdx.z;
    const int n0 = blockIdx.x * BN;
    const int m0 = blockIdx.y * BM;
    const float* Xp = xg + (size_t)bb * C_ * HW_;

    float acc[8][8];
#pragma unroll
    for (int i = 0; i < 8; ++i)
#pragma unroll
        for (int j = 0; j < 8; ++j) acc[i][j] = 0.f;

    const int ar = tid >> 2;
    const int ak = (tid & 3) << 2;
    const int br = tid >> 5;
    const int bc = (tid & 31) << 2;

    for (int kt = 0; kt < C_; kt += BK) {
        float4 a0 = *(const float4*)(t_w + (size_t)(m0 + ar)      * C_ + kt + ak);
        float4 a1 = *(const float4*)(t_w + (size_t)(m0 + ar + 64) * C_ + kt + ak);
        float4 b0, b1;
        {
            const int c0 = kt + br;
            float4 xv = *(const float4*)(Xp + (size_t)c0 * HW_ + n0 + bc);
            float tv[4];
#pragma unroll
            for (int e = 0; e < 4; ++e) {
                const int n = n0 + bc + e;
                const int w = n & 7, h = n >> 3;
                tv[e] = ((const float*)&xv)[e]
                      - g_xrT[(((size_t)bb * W_ + w) * C_ + c0) * H_ + h];
            }
            b0 = make_float4(tv[0], tv[1], tv[2], tv[3]);
        }
        {
            const int c1 = kt + br + 8;
            float4 xv = *(const float4*)(Xp + (size_t)c1 * HW_ + n0 + bc);
            float tv[4];
#pragma unroll
            for (int e = 0; e < 4; ++e) {
                const int n = n0 + bc + e;
                const int w = n & 7, h = n >> 3;
                tv[e] = ((const float*)&xv)[e]
                      - g_xrT[(((size_t)bb * W_ + w) * C_ + c1) * H_ + h];
            }
            b1 = make_float4(tv[0], tv[1], tv[2], tv[3]);
        }
        __syncthreads();
        As[ak + 0][ar]      = a0.x; As[ak + 1][ar]      = a0.y;
        As[ak + 2][ar]      = a0.z; As[ak + 3][ar]      = a0.w;
        As[ak + 0][ar + 64] = a1.x; As[ak + 1][ar + 64] = a1.y;
        As[ak + 2][ar + 64] = a1.z; As[ak + 3][ar + 64] = a1.w;
        *(float4*)&Bs[br][bc]     = b0;
        *(float4*)&Bs[br + 8][bc] = b1;
        __syncthreads();
#pragma unroll
        for (int k = 0; k < BK; ++k) {
            float a[8], b[8];
            *(float4*)&a[0] = *(const float4*)&As[k][ty * 4];
            *(float4*)&a[4] = *(const float4*)&As[k][64 + ty * 4];
            *(float4*)&b[0] = *(const float4*)&Bs[k][tx * 4];
            *(float4*)&b[4] = *(const float4*)&Bs[k][64 + tx * 4];
#pragma unroll
            for (int i = 0; i < 8; ++i)
#pragma unroll
                for (int j = 0; j < 8; ++j)
                    acc[i][j] = fmaf(a[i], b[j], acc[i][j]);
        }
    }

    float* Op = out + (size_t)bb * C_ * HW_;
#pragma unroll
    for (int i = 0; i < 8; ++i) {
        const int m = m0 + ((i < 4) ? (ty * 4 + i) : (64 + ty * 4 + i - 4));
        const float bv = t_b[m];
        *(float4*)(Op + (size_t)m * HW_ + n0 + tx * 4) =
            make_float4(acc[i][0] + bv, acc[i][1] + bv, acc[i][2] + bv, acc[i][3] + bv);
        *(float4*)(Op + (size_t)m * HW_ + n0 + 64 + tx * 4) =
            make_float4(acc[i][4] + bv, acc[i][5] + bv, acc[i][6] + bv, acc[i][7] + bv);
    }
}

// =====================================================================
// BN statistics + finalize + residual/ReLU
// =====================================================================
__global__ void k_zero() { if (threadIdx.x < 2 * C_) g_chan[threadIdx.x] = 0.f; }

__global__ void k_chansum(const float* __restrict__ t)
{
    const int c = blockIdx.x, b = blockIdx.y;
    const float4* p = (const float4*)(t + ((size_t)b * C_ + c) * HW_);
    float s = 0.f, q = 0.f;
    for (int i = threadIdx.x; i < HW_ / 4; i += 256) {
        float4 v = p[i];
        s += v.x + v.y + v.z + v.w;
        q += v.x * v.x + v.y * v.y + v.z * v.z + v.w * v.w;
    }
    __shared__ float ss[256], sq[256];
    ss[threadIdx.x] = s; sq[threadIdx.x] = q;
    __syncthreads();
    for (int o = 128; o > 0; o >>= 1) {
        if (threadIdx.x < o) {
            ss[threadIdx.x] += ss[threadIdx.x + o];
            sq[threadIdx.x] += sq[threadIdx.x + o];
        }
        __syncthreads();
    }
    if (threadIdx.x == 0) {
        atomicAdd(&g_chan[c],      ss[0]);
        atomicAdd(&g_chan[C_ + c], sq[0]);
    }
}

__global__ void k_bnfin(const float* __restrict__ gamma, const float* __restrict__ beta)
{
    const int c = threadIdx.x;
    const float n = (float)(B_ * HW_);
    const float mean = g_chan[c] / n;
    const float var  = g_chan[C_ + c] / n - mean * mean;
    const float sc = gamma[c] * rsqrtf(var + 1e-5f);
    g_bn[c]      = sc;
    g_bn[C_ + c] = beta[c] - mean * sc;
}

__global__ void k_final(const float* __restrict__ xg, float* __restrict__ out)
{
    const size_t i4 = (size_t)blockIdx.x * 256 + threadIdx.x;
    const int c = (int)((i4 >> 11) & 511);
    const float sc = g_bn[c], sh = g_bn[C_ + c];
    float4 t  = ((const float4*)out)[i4];
    float4 xv = ((const float4*)xg)[i4];
    float4 o;
    o.x = xv.x + fmaxf(0.f, fmaf(t.x, sc, sh));
    o.y = xv.y + fmaxf(0.f, fmaf(t.y, sc, sh));
    o.z = xv.z + fmaxf(0.f, fmaf(t.z, sc, sh));
    o.w = xv.w + fmaxf(0.f, fmaf(t.w, sc, sh));
    ((float4*)out)[i4] = o;
}

// =====================================================================
// launch
// =====================================================================
extern "C" void kernel_launch(void* const* d_in, const int* in_sizes, int n_in,
                              void* d_out, int out_size)
{
    (void)in_sizes; (void)n_in; (void)out_size;
    const float* x     = (const float*)d_in[0];
    const float* qk_w  = (const float*)d_in[1];
    const float* v_w   = (const float*)d_in[2];
    const float* v_b   = (const float*)d_in[3];
    const float* t_w   = (const float*)d_in[4];
    const float* t_b   = (const float*)d_in[5];
    const float* gamma = (const float*)d_in[6];
    const float* beta  = (const float*)d_in[7];
    float* out = (float*)d_out;

    cudaFuncSetAttribute(k_hmma, cudaFuncAttributeMaxDynamicSharedMemorySize, DYN_SMEM);

    k_zero   <<<1, 1024>>>();
    k_proj   <<<dim3(HW_ / BN, C4_ / BM, B_), 256>>>(qk_w, x, nullptr, C4_, 0);
    k_proj   <<<dim3(HW_ / BN, C_  / BM, B_), 256>>>(v_w,  x, v_b,     C_,  1);
    k_hmma   <<<dim3(8, 8, NSL_), 256, DYN_SMEM>>>(0);   // energy (bf16x3 mma.sync)
    k_softmax<<<dim3(H_, NSL_),   256>>>();
    k_hmma   <<<dim3(8, 4, NSL_), 256, DYN_SMEM>>>(1);   // apply  (bf16x3 mma.sync)
    k_trans  <<<dim3(HW_ / BN, C_ / BM, B_), 256>>>(t_w, t_b, x, out);
    k_chansum<<<dim3(C_, B_), 256>>>(out);
    k_bnfin  <<<1, C_>>>(gamma, beta);
    k_final  <<<(B_ * C_ * HW_) / 4 / 256, 256>>>(x, out);
}

// round 17
// speedup vs baseline: 1.2306x; 1.0002x over previous
#include <cuda_runtime.h>
#include <cuda_bf16.h>
#include <math.h>
#include <stdint.h>

// ---------------- problem constants ----------------
#define B_   8
#define C_   512
#define C4_  128
#define H_   1024
#define W_   8
#define HW_  8192
#define NSL_ 64

// ---------------- FFMA GEMM tile constants ----------------
#define BM 128
#define BN 128
#define BK 16
#define AST 132

// ---------------- scratch ----------------
__device__ float g_qT [8388608];    // [b][w][h][d]  (d contiguous)      32 MB
__device__ float g_vT [33554432];   // [b][w][c][h]                     128 MB
__device__ float g_att[67108864];   // E[i][j] -> attT[j][i] in place   256 MB
__device__ float g_xrT[33554432];   // [b][w][c][h]                     128 MB
__device__ float g_chan[2 * C_];
__device__ float g_bn  [2 * C_];

// =====================================================================
// bf16x3 mma.sync GEMM:  C[m,n] = sum_k A[z][m,k] * B[z][n,k]
// CTA 128x128, 8 warps (32x64 each), K-chunk 32, double-buffered smem.
// mode 0: energy (A=B=q[s][h][d], K=128, out=E[i][j])
// mode 1: apply  (A=V[s][c][h],  B=attT[s][j][i], K=1024, out=xr[s][c][j])
// =====================================================================
#define PADK  40            // bf16 per smem row (32 data + 8 pad)
#define PADB  80            // bytes per smem row
#define ARR_B 10240         // 128 * PADB
#define STG_B 40960         // 4 arrays per stage
#define DYN_SMEM (2 * STG_B)

__device__ __forceinline__ uint32_t pk_hi(float a, float b) {
    __nv_bfloat162 h = __floats2bfloat162_rn(a, b);
    return *(uint32_t*)&h;
}
__device__ __forceinline__ void split2(float a, float b, uint32_t& hi, uint32_t& lo) {
    __nv_bfloat16 ha = __float2bfloat16(a);
    __nv_bfloat16 hb = __float2bfloat16(b);
    float la = a - __bfloat162float(ha);
    float lb = b - __bfloat162float(hb);
    __nv_bfloat162 h2; h2.x = ha; h2.y = hb;
    hi = *(uint32_t*)&h2;
    __nv_bfloat162 l2 = __floats2bfloat162_rn(la, lb);
    lo = *(uint32_t*)&l2;
}

#define MMA_BF16(c0,c1,c2,c3,a0,a1,a2,a3,b0,b1)                              \
    asm volatile(                                                            \
        "mma.sync.aligned.m16n8k16.row.col.f32.bf16.bf16.f32 "               \
        "{%0,%1,%2,%3}, {%4,%5,%6,%7}, {%8,%9}, {%0,%1,%2,%3};"              \
        : "+f"(c0), "+f"(c1), "+f"(c2), "+f"(c3)                             \
        : "r"(a0), "r"(a1), "r"(a2), "r"(a3), "r"(b0), "r"(b1))

__global__ __launch_bounds__(256, 1) void k_hmma(int mode)
{
    extern __shared__ char sm[];

    const float *A, *Bm;
    float* O;
    long sA, sB, sO;
    int lda, ldb, ldo, K;
    if (mode == 0) {
        A = g_qT; Bm = g_qT; O = g_att;
        sA = sB = (long)H_ * C4_; lda = ldb = C4_;
        sO = (long)H_ * H_; ldo = H_; K = C4_;
    } else {
        A = g_vT; Bm = g_att; O = g_xrT;
        sA = (long)C_ * H_; lda = H_;
        sB = (long)H_ * H_; ldb = H_;
        sO = (long)C_ * H_; ldo = H_; K = H_;
    }

    const int tid  = threadIdx.x;
    const int lane = tid & 31, wid = tid >> 5;
    const int wm = wid >> 1, wn = wid & 1;       // warp grid 4(m) x 2(n)
    const int g  = lane >> 2;                    // 0..7
    const int l2 = (lane & 3) * 2;               // 0,2,4,6
    const int z  = blockIdx.z;
    const int n0 = blockIdx.x * 128;
    const int m0 = blockIdx.y * 128;

    const float* Ab = A  + (size_t)z * sA + (size_t)m0 * lda;
    const float* Bb = Bm + (size_t)z * sB + (size_t)n0 * ldb;

    // staging: thread -> (row = tid>>1, k-half = (tid&1)*16), 4 float4 each operand
    const int r     = tid >> 1;
    const int halfk = (tid & 1) * 16;

    float acc[2][8][4];
#pragma unroll
    for (int mt = 0; mt < 2; ++mt)
#pragma unroll
        for (int nt = 0; nt < 8; ++nt)
#pragma unroll
            for (int e = 0; e < 4; ++e) acc[mt][nt][e] = 0.f;

    const int niter = K / 32;

    // ---- stage chunk 0 ----
    {
        const float* ga = Ab + (size_t)r * lda + halfk;
        const float* gb = Bb + (size_t)r * ldb + halfk;
        char* AH = sm;            char* AL = sm + ARR_B;
        char* BH = sm + 2*ARR_B;  char* BL = sm + 3*ARR_B;
        const int ob = r * PADB + halfk * 2;
#pragma unroll
        for (int q = 0; q < 4; ++q) {
            float4 va = *(const float4*)(ga + q * 4);
            uint32_t h0, l0, h1, l1;
            split2(va.x, va.y, h0, l0); split2(va.z, va.w, h1, l1);
            *(uint2*)(AH + ob + q * 8) = make_uint2(h0, h1);
            *(uint2*)(AL + ob + q * 8) = make_uint2(l0, l1);
            float4 vb = *(const float4*)(gb + q * 4);
            split2(vb.x, vb.y, h0, l0); split2(vb.z, vb.w, h1, l1);
            *(uint2*)(BH + ob + q * 8) = make_uint2(h0, h1);
            *(uint2*)(BL + ob + q * 8) = make_uint2(l0, l1);
        }
    }
    __syncthreads();

    for (int it = 0; it < niter; ++it) {
        // prefetch next chunk into registers
        float4 pa[4], pb[4];
        if (it + 1 < niter) {
            const float* ga = Ab + (size_t)r * lda + (it + 1) * 32 + halfk;
            const float* gb = Bb + (size_t)r * ldb + (it + 1) * 32 + halfk;
#pragma unroll
            for (int q = 0; q < 4; ++q) { pa[q] = *(const float4*)(ga + q * 4);
                                          pb[q] = *(const float4*)(gb + q * 4); }
        }

        // compute from current buffer
        {
            const char* base = sm + (it & 1) * STG_B;
            const char* AH = base;            const char* AL = base + ARR_B;
            const char* BH = base + 2*ARR_B;  const char* BL = base + 3*ARR_B;
#pragma unroll
            for (int ks = 0; ks < 2; ++ks) {
                const int kb2 = (ks * 16 + l2) * 2;
                uint32_t ah[2][4], al_[2][4];
#pragma unroll
                for (int mt = 0; mt < 2; ++mt) {
                    const int ro = (wm * 32 + mt * 16 + g) * PADB + kb2;
                    ah[mt][0]  = *(const uint32_t*)(AH + ro);
                    ah[mt][1]  = *(const uint32_t*)(AH + ro + 8 * PADB);
                    ah[mt][2]  = *(const uint32_t*)(AH + ro + 16);
                    ah[mt][3]  = *(const uint32_t*)(AH + ro + 8 * PADB + 16);
                    al_[mt][0] = *(const uint32_t*)(AL + ro);
                    al_[mt][1] = *(const uint32_t*)(AL + ro + 8 * PADB);
                    al_[mt][2] = *(const uint32_t*)(AL + ro + 16);
                    al_[mt][3] = *(const uint32_t*)(AL + ro + 8 * PADB + 16);
                }
#pragma unroll
                for (int nt = 0; nt < 8; ++nt) {
                    const int bo = (wn * 64 + nt * 8 + g) * PADB + kb2;
                    uint32_t bh0 = *(const uint32_t*)(BH + bo);
                    uint32_t bh1 = *(const uint32_t*)(BH + bo + 16);
                    uint32_t bl0 = *(const uint32_t*)(BL + bo);
                    uint32_t bl1 = *(const uint32_t*)(BL + bo + 16);
#pragma unroll
                    for (int mt = 0; mt < 2; ++mt) {
                        float* c = acc[mt][nt];
                        MMA_BF16(c[0], c[1], c[2], c[3],
                                 ah[mt][0], ah[mt][1], ah[mt][2], ah[mt][3], bh0, bh1);
                        MMA_BF16(c[0], c[1], c[2], c[3],
                                 ah[mt][0], ah[mt][1], ah[mt][2], ah[mt][3], bl0, bl1);
                        MMA_BF16(c[0], c[1], c[2], c[3],
                                 al_[mt][0], al_[mt][1], al_[mt][2], al_[mt][3], bh0, bh1);
                    }
                }
            }
        }

        // store prefetched chunk to other buffer
        if (it + 1 < niter) {
            char* base = sm + ((it + 1) & 1) * STG_B;
            char* AH = base;            char* AL = base + ARR_B;
            char* BH = base + 2*ARR_B;  char* BL = base + 3*ARR_B;
            const int ob = r * PADB + halfk * 2;
#pragma unroll
            for (int q = 0; q < 4; ++q) {
                uint32_t h0, l0, h1, l1;
                split2(pa[q].x, pa[q].y, h0, l0); split2(pa[q].z, pa[q].w, h1, l1);
                *(uint2*)(AH + ob + q * 8) = make_uint2(h0, h1);
                *(uint2*)(AL + ob + q * 8) = make_uint2(l0, l1);
                split2(pb[q].x, pb[q].y, h0, l0); split2(pb[q].z, pb[q].w, h1, l1);
                *(uint2*)(BH + ob + q * 8) = make_uint2(h0, h1);
                *(uint2*)(BL + ob + q * 8) = make_uint2(l0, l1);
            }
            __syncthreads();
        }
    }

    // epilogue
    float* Ob = O + (size_t)z * sO;
#pragma unroll
    for (int mt = 0; mt < 2; ++mt) {
        const int row = m0 + wm * 32 + mt * 16 + g;
#pragma unroll
        for (int nt = 0; nt < 8; ++nt) {
            const int col = n0 + wn * 64 + nt * 8 + l2;
            *(float2*)(Ob + (size_t)row * ldo + col)       = make_float2(acc[mt][nt][0], acc[mt][nt][1]);
            *(float2*)(Ob + (size_t)(row + 8) * ldo + col) = make_float2(acc[mt][nt][2], acc[mt][nt][3]);
        }
    }
}

// =====================================================================
// projections (FFMA). which==0 (q): out [s][h][d]; which==1 (v): [s][c][h]
// =====================================================================
__global__ __launch_bounds__(256) void k_proj(const float* __restrict__ Wm,
                                              const float* __restrict__ xg,
                                              const float* __restrict__ bias,
                                              int M, int which)
{
    __shared__ __align__(16) float As[BK][AST];
    __shared__ __align__(16) float Bs[BK][BN];
    const int tid = threadIdx.x;
    const int tx = tid & 15, ty = tid >> 4;
    const int bb = blockIdx.z;
    const int n0 = blockIdx.x * BN;
    const int m0 = blockIdx.y * BM;
    const float* Bp = xg + (size_t)bb * C_ * HW_;

    float acc[8][8];
#pragma unroll
    for (int i = 0; i < 8; ++i)
#pragma unroll
        for (int j = 0; j < 8; ++j) acc[i][j] = 0.f;

    const int ar = tid >> 2;
    const int ak = (tid & 3) << 2;
    const int br = tid >> 5;
    const int bc = (tid & 31) << 2;

    for (int kt = 0; kt < C_; kt += BK) {
        float4 a0 = *(const float4*)(Wm + (size_t)(m0 + ar)      * C_  + kt + ak);
        float4 a1 = *(const float4*)(Wm + (size_t)(m0 + ar + 64) * C_  + kt + ak);
        float4 b0 = *(const float4*)(Bp + (size_t)(kt + br)      * HW_ + n0 + bc);
        float4 b1 = *(const float4*)(Bp + (size_t)(kt + br + 8)  * HW_ + n0 + bc);
        __syncthreads();
        As[ak + 0][ar]      = a0.x; As[ak + 1][ar]      = a0.y;
        As[ak + 2][ar]      = a0.z; As[ak + 3][ar]      = a0.w;
        As[ak + 0][ar + 64] = a1.x; As[ak + 1][ar + 64] = a1.y;
        As[ak + 2][ar + 64] = a1.z; As[ak + 3][ar + 64] = a1.w;
        *(float4*)&Bs[br][bc]     = b0;
        *(float4*)&Bs[br + 8][bc] = b1;
        __syncthreads();
#pragma unroll
        for (int k = 0; k < BK; ++k) {
            float a[8], b[8];
            *(float4*)&a[0] = *(const float4*)&As[k][ty * 4];
            *(float4*)&a[4] = *(const float4*)&As[k][64 + ty * 4];
            *(float4*)&b[0] = *(const float4*)&Bs[k][tx * 4];
            *(float4*)&b[4] = *(const float4*)&Bs[k][64 + tx * 4];
#pragma unroll
            for (int i = 0; i < 8; ++i)
#pragma unroll
                for (int j = 0; j < 8; ++j)
                    acc[i][j] = fmaf(a[i], b[j], acc[i][j]);
        }
    }

#pragma unroll
    for (int i = 0; i < 8; ++i) {
        const int m = m0 + ((i < 4) ? (ty * 4 + i) : (64 + ty * 4 + i - 4));
        const float bv = bias ? bias[m] : 0.f;
#pragma unroll
        for (int j = 0; j < 8; ++j) {
            const int n = n0 + ((j < 4) ? (tx * 4 + j) : (64 + tx * 4 + j - 4));
            const int w = n & 7, h = n >> 3;
            if (which)
                g_vT[(((size_t)bb * W_ + w) * C_ + m) * H_ + h] = acc[i][j] + bv;
            else
                g_qT[(((size_t)bb * W_ + w) * H_ + h) * C4_ + m] = acc[i][j] + bv;
        }
    }
}

// =====================================================================
// Row softmax on symmetric E (E[i,j]==E[j,i] bitwise); writes attT[j][i]
// in place. Block j reads/writes only row j.
// =====================================================================
__global__ void k_softmax()
{
    const int j = blockIdx.x, s = blockIdx.y;
    float* row = g_att + ((size_t)s * H_ + j) * H_;
    const int tid = threadIdx.x, lane = tid & 31, wid = tid >> 5;
    __shared__ float rbuf[8];

    float4 v = ((const float4*)row)[tid];
    float m4 = fmaxf(fmaxf(v.x, v.y), fmaxf(v.z, v.w));
#pragma unroll
    for (int o = 16; o > 0; o >>= 1) m4 = fmaxf(m4, __shfl_xor_sync(0xffffffffu, m4, o));
    if (lane == 0) rbuf[wid] = m4;
    __syncthreads();
    float m = rbuf[0];
#pragma unroll
    for (int k = 1; k < 8; ++k) m = fmaxf(m, rbuf[k]);
    __syncthreads();

    float4 e;
    e.x = __expf(v.x - m); e.y = __expf(v.y - m);
    e.z = __expf(v.z - m); e.w = __expf(v.w - m);
    float s4 = e.x + e.y + e.z + e.w;
#pragma unroll
    for (int o = 16; o > 0; o >>= 1) s4 += __shfl_xor_sync(0xffffffffu, s4, o);
    if (lane == 0) rbuf[wid] = s4;
    __syncthreads();
    float sum = rbuf[0];
#pragma unroll
    for (int k = 1; k < 8; ++k) sum += rbuf[k];

    const float inv = 1.0f / (sum * (1.0f + 1e-9f));
    ((float4*)row)[tid] = make_float4(e.x * inv, e.y * inv, e.z * inv, e.w * inv);
}

// =====================================================================
// t = t_w @ (x - x_r) + t_b  -> d_out  (FFMA)
// =====================================================================
__global__ __launch_bounds__(256) void k_trans(const float* __restrict__ t_w,
                                               const float* __restrict__ t_b,
                                               const float* __restrict__ xg,
                                               float* __restrict__ out)
{
    __shared__ __align__(16) float As[BK][AST];
    __shared__ __align__(16) float Bs[BK][BN];
    const int tid = threadIdx.x;
    const int tx = tid & 15, ty = tid >> 4;
    const int bb = blockIdx.z;
    const int n0 = blockIdx.x * BN;
    const int m0 = blockIdx.y * BM;
    const float* Xp = xg + (size_t)bb * C_ * HW_;

    float acc[8][8];
#pragma unroll
    for (int i = 0; i < 8; ++i)
#pragma unroll
        for (int j = 0; j < 8; ++j) acc[i][j] = 0.f;

    const int ar = tid >> 2;
    const int ak = (tid & 3) << 2;
    const int br = tid >> 5;
    const int bc = (tid & 31) << 2;

    for (int kt = 0; kt < C_; kt += BK) {
        float4 a0 = *(const float4*)(t_w + (size_t)(m0 + ar)      * C_ + kt + ak);
        float4 a1 = *(const float4*)(t_w + (size_t)(m0 + ar + 64) * C_ + kt + ak);
        float4 b0, b1;
        {
            const int c0 = kt + br;
            float4 xv = *(const float4*)(Xp + (size_t)c0 * HW_ + n0 + bc);
            float tv[4];
#pragma unroll
            for (int e = 0; e < 4; ++e) {
                const int n = n0 + bc + e;
                const int w = n & 7, h = n >> 3;
                tv[e] = ((const float*)&xv)[e]
                      - g_xrT[(((size_t)bb * W_ + w) * C_ + c0) * H_ + h];
            }
            b0 = make_float4(tv[0], tv[1], tv[2], tv[3]);
        }
        {
            const int c1 = kt + br + 8;
            float4 xv = *(const float4*)(Xp + (size_t)c1 * HW_ + n0 + bc);
            float tv[4];
#pragma unroll
            for (int e = 0; e < 4; ++e) {
                const int n = n0 + bc + e;
                const int w = n & 7, h = n >> 3;
                tv[e] = ((const float*)&xv)[e]
                      - g_xrT[(((size_t)bb * W_ + w) * C_ + c1) * H_ + h];
            }
            b1 = make_float4(tv[0], tv[1], tv[2], tv[3]);
        }
        __syncthreads();
        As[ak + 0][ar]      = a0.x; As[ak + 1][ar]      = a0.y;
        As[ak + 2][ar]      = a0.z; As[ak + 3][ar]      = a0.w;
        As[ak + 0][ar + 64] = a1.x; As[ak + 1][ar + 64] = a1.y;
        As[ak + 2][ar + 64] = a1.z; As[ak + 3][ar + 64] = a1.w;
        *(float4*)&Bs[br][bc]     = b0;
        *(float4*)&Bs[br + 8][bc] = b1;
        __syncthreads();
#pragma unroll
        for (int k = 0; k < BK; ++k) {
            float a[8], b[8];
            *(float4*)&a[0] = *(const float4*)&As[k][ty * 4];
            *(float4*)&a[4] = *(const float4*)&As[k][64 + ty * 4];
            *(float4*)&b[0] = *(const float4*)&Bs[k][tx * 4];
            *(float4*)&b[4] = *(const float4*)&Bs[k][64 + tx * 4];
#pragma unroll
            for (int i = 0; i < 8; ++i)
#pragma unroll
                for (int j = 0; j < 8; ++j)
                    acc[i][j] = fmaf(a[i], b[j], acc[i][j]);
        }
    }

    float* Op = out + (size_t)bb * C_ * HW_;
#pragma unroll
    for (int i = 0; i < 8; ++i) {
        const int m = m0 + ((i < 4) ? (ty * 4 + i) : (64 + ty * 4 + i - 4));
        const float bv = t_b[m];
        *(float4*)(Op + (size_t)m * HW_ + n0 + tx * 4) =
            make_float4(acc[i][0] + bv, acc[i][1] + bv, acc[i][2] + bv, acc[i][3] + bv);
        *(float4*)(Op + (size_t)m * HW_ + n0 + 64 + tx * 4) =
            make_float4(acc[i][4] + bv, acc[i][5] + bv, acc[i][6] + bv, acc[i][7] + bv);
    }
}

// =====================================================================
// BN statistics + finalize + residual/ReLU
// =====================================================================
__global__ void k_zero() { if (threadIdx.x < 2 * C_) g_chan[threadIdx.x] = 0.f; }

__global__ void k_chansum(const float* __restrict__ t)
{
    const int c = blockIdx.x, b = blockIdx.y;
    const float4* p = (const float4*)(t + ((size_t)b * C_ + c) * HW_);
    float s = 0.f, q = 0.f;
    for (int i = threadIdx.x; i < HW_ / 4; i += 256) {
        float4 v = p[i];
        s += v.x + v.y + v.z + v.w;
        q += v.x * v.x + v.y * v.y + v.z * v.z + v.w * v.w;
    }
    __shared__ float ss[256], sq[256];
    ss[threadIdx.x] = s; sq[threadIdx.x] = q;
    __syncthreads();
    for (int o = 128; o > 0; o >>= 1) {
        if (threadIdx.x < o) {
            ss[threadIdx.x] += ss[threadIdx.x + o];
            sq[threadIdx.x] += sq[threadIdx.x + o];
        }
        __syncthreads();
    }
    if (threadIdx.x == 0) {
        atomicAdd(&g_chan[c],      ss[0]);
        atomicAdd(&g_chan[C_ + c], sq[0]);
    }
}

__global__ void k_bnfin(const float* __restrict__ gamma, const float* __restrict__ beta)
{
    const int c = threadIdx.x;
    const float n = (float)(B_ * HW_);
    const float mean = g_chan[c] / n;
    const float var  = g_chan[C_ + c] / n - mean * mean;
    const float sc = gamma[c] * rsqrtf(var + 1e-5f);
    g_bn[c]      = sc;
    g_bn[C_ + c] = beta[c] - mean * sc;
}

__global__ void k_final(const float* __restrict__ xg, float* __restrict__ out)
{
    const size_t i4 = (size_t)blockIdx.x * 256 + threadIdx.x;
    const int c = (int)((i4 >> 11) & 511);
    const float sc = g_bn[c], sh = g_bn[C_ + c];
    float4 t  = ((const float4*)out)[i4];
    float4 xv = ((const float4*)xg)[i4];
    float4 o;
    o.x = xv.x + fmaxf(0.f, fmaf(t.x, sc, sh));
    o.y = xv.y + fmaxf(0.f, fmaf(t.y, sc, sh));
    o.z = xv.z + fmaxf(0.f, fmaf(t.z, sc, sh));
    o.w = xv.w + fmaxf(0.f, fmaf(t.w, sc, sh));
    ((float4*)out)[i4] = o;
}

// =====================================================================
// launch
// =====================================================================
extern "C" void kernel_launch(void* const* d_in, const int* in_sizes, int n_in,
                              void* d_out, int out_size)
{
    (void)in_sizes; (void)n_in; (void)out_size;
    const float* x     = (const float*)d_in[0];
    const float* qk_w  = (const float*)d_in[1];
    const float* v_w   = (const float*)d_in[2];
    const float* v_b   = (const float*)d_in[3];
    const float* t_w   = (const float*)d_in[4];
    const float* t_b   = (const float*)d_in[5];
    const float* gamma = (const float*)d_in[6];
    const float* beta  = (const float*)d_in[7];
    float* out = (float*)d_out;

    cudaFuncSetAttribute(k_hmma, cudaFuncAttributeMaxDynamicSharedMemorySize, DYN_SMEM);

    k_zero   <<<1, 1024>>>();
    k_proj   <<<dim3(HW_ / BN, C4_ / BM, B_), 256>>>(qk_w, x, nullptr, C4_, 0);
    k_proj   <<<dim3(HW_ / BN, C_  / BM, B_), 256>>>(v_w,  x, v_b,     C_,  1);
    k_hmma   <<<dim3(8, 8, NSL_), 256, DYN_SMEM>>>(0);   // energy (bf16x3 mma.sync)
    k_softmax<<<dim3(H_, NSL_),   256>>>();
    k_hmma   <<<dim3(8, 4, NSL_), 256, DYN_SMEM>>>(1);   // apply  (bf16x3 mma.sync)
    k_trans  <<<dim3(HW_ / BN, C_ / BM, B_), 256>>>(t_w, t_b, x, out);
    k_chansum<<<dim3(C_, B_), 256>>>(out);
    k_bnfin  <<<1, C_>>>(gamma, beta);
    k_final  <<<(B_ * C_ * HW_) / 4 / 256, 256>>>(x, out);
}